// round 2
// baseline (speedup 1.0000x reference)
#include <cuda_runtime.h>
#include <cstring>

// Problem constants
#define BB 128
#define TT 512
#define II 128
#define HH 256

// Intermediate xp buffer: [B][T][H] fp32 = 64 MB (static device array: no allocs allowed)
__device__ float g_xp[(size_t)BB * TT * HH];

// Packed fp32x2 FMA (sm_103a): d = a*b + c on two lanes in one issue.
__device__ __forceinline__ float2 ffma2(float2 a, float2 b, float2 c) {
    unsigned long long ua, ub, uc, ud;
    memcpy(&ua, &a, 8); memcpy(&ub, &b, 8); memcpy(&uc, &c, 8);
    asm("fma.rn.f32x2 %0, %1, %2, %3;" : "=l"(ud) : "l"(ua), "l"(ub), "l"(uc));
    float2 d; memcpy(&d, &ud, 8); return d;
}

// ---------------------------------------------------------------------------
// Phase 1: xp[b,t,h] = sum_i x[b,t,i] * W_ih[h,i] + (b_ih[h] + b_hh[h])
// Grid: 512 CTAs x 256 threads. Each CTA handles 128 rows of the flattened
// (B*T, I) matrix. Thread h holds W_ih row h (128 fp32 = 32 float4) in regs.
// ---------------------------------------------------------------------------
__global__ void __launch_bounds__(256, 1)
rnn_xproj(const float* __restrict__ x,
          const float* __restrict__ W_ih,
          const float* __restrict__ b_ih,
          const float* __restrict__ b_hh) {
    __shared__ float xs[8 * II];   // 8 rows of x staged per tile (4 KB)

    const int h = threadIdx.x;     // output feature 0..255

    // W_ih row h -> registers (one-time, L2-resident after first CTA)
    const float4* Wi4 = (const float4*)W_ih;
    float4 wreg[32];
#pragma unroll
    for (int q = 0; q < 32; q++) wreg[q] = Wi4[h * 32 + q];

    const float bias = b_ih[h] + b_hh[h];

    const size_t base_row = (size_t)blockIdx.x * 128;

    for (int tile = 0; tile < 16; tile++) {       // 16 tiles x 8 rows = 128 rows
        const size_t r0 = base_row + (size_t)tile * 8;
        // cooperative load of 8 x-rows (8*128 floats = 256 float4, one per thread)
        ((float4*)xs)[h] = ((const float4*)(x + r0 * II))[h];
        __syncthreads();

#pragma unroll
        for (int r = 0; r < 8; r++) {
            const float4* xr = (const float4*)(xs + r * II);
            float2 aa = make_float2(bias, 0.0f);
            float2 ab = make_float2(0.0f, 0.0f);
#pragma unroll
            for (int q = 0; q < 32; q++) {
                float4 xv = xr[q];
                aa = ffma2(make_float2(xv.x, xv.y),
                           make_float2(wreg[q].x, wreg[q].y), aa);
                ab = ffma2(make_float2(xv.z, xv.w),
                           make_float2(wreg[q].z, wreg[q].w), ab);
            }
            g_xp[(r0 + r) * HH + h] = aa.x + aa.y + ab.x + ab.y;
        }
        __syncthreads();
    }
}

// ---------------------------------------------------------------------------
// Phase 2 + 3: per-batch recurrent scan. 128 CTAs (one per batch row),
// 256 threads (thread j owns output feature j).
//   - W_hh[j][0:192]   in registers (48 float4 per thread)
//   - W_hh[j][192:256] in SMEM, laid out [q16][j] as float4 (conflict-free)
//   - h in SMEM, read via broadcast float4 loads
//   - xp_t streamed from gmem (coalesced 1KB/step, latency hidden by the dot)
// Epilogue: logit = h . W_fc + b_fc, out[b] = sigmoid(logit).
// ---------------------------------------------------------------------------
__global__ void __launch_bounds__(256, 1)
rnn_scan(const float* __restrict__ W_hh,
         const float* __restrict__ W_fc,
         const float* __restrict__ b_fc,
         float* __restrict__ out) {
    extern __shared__ float sm[];
    float4* wt4 = (float4*)sm;              // [16][256] float4 = 64 KB (W tail)
    float*  hs  = sm + 16 * HH * 4;         // 256 floats (current h)
    float*  red = hs + HH;                  // 8 floats (warp partials)

    const int j = threadIdx.x;
    const int b = blockIdx.x;

    const float4* W4 = (const float4*)W_hh;   // row j = W4[j*64 .. j*64+63]

    // k = 0..191 -> registers
    float4 wreg[48];
#pragma unroll
    for (int q = 0; q < 48; q++) wreg[q] = W4[j * 64 + q];

    // k = 192..255 -> SMEM transposed-by-chunk: wt4[q16*256 + j2]
    for (int idx = j; idx < 16 * 256; idx += 256) {
        const int q16 = idx >> 8;
        const int j2  = idx & 255;
        wt4[q16 * 256 + j2] = W4[j2 * 64 + 48 + q16];
    }

    hs[j] = 0.0f;
    __syncthreads();

    const float* xp = g_xp + (size_t)b * TT * HH;
    float hn = 0.0f;

    for (int t = 0; t < TT; t++) {
        const float xpv = xp[t * HH + j];     // issued early; consumed after dot

        const float4* hs4 = (const float4*)hs;
        float2 aa = make_float2(0.0f, 0.0f);
        float2 ab = make_float2(0.0f, 0.0f);

#pragma unroll
        for (int q = 0; q < 48; q++) {
            float4 h4 = hs4[q];
            aa = ffma2(make_float2(h4.x, h4.y),
                       make_float2(wreg[q].x, wreg[q].y), aa);
            ab = ffma2(make_float2(h4.z, h4.w),
                       make_float2(wreg[q].z, wreg[q].w), ab);
        }
#pragma unroll
        for (int q = 0; q < 16; q++) {
            float4 h4 = hs4[48 + q];
            float4 w4 = wt4[q * 256 + j];
            aa = ffma2(make_float2(h4.x, h4.y), make_float2(w4.x, w4.y), aa);
            ab = ffma2(make_float2(h4.z, h4.w), make_float2(w4.z, w4.w), ab);
        }

        const float s = aa.x + aa.y + ab.x + ab.y;
        hn = tanhf(xpv + s);

        __syncthreads();          // everyone done reading hs
        hs[j] = hn;
        __syncthreads();          // new h visible
    }

    // Phase 3: logits = h . W_fc[0,:] + b_fc[0]; out = sigmoid
    float v = hn * W_fc[j];
#pragma unroll
    for (int o = 16; o > 0; o >>= 1) v += __shfl_down_sync(0xffffffffu, v, o);
    if ((j & 31) == 0) red[j >> 5] = v;
    __syncthreads();
    if (j == 0) {
        float s = b_fc[0];
#pragma unroll
        for (int w = 0; w < 8; w++) s += red[w];
        out[b] = 1.0f / (1.0f + expf(-s));
    }
}

// ---------------------------------------------------------------------------

extern "C" void kernel_launch(void* const* d_in, const int* in_sizes, int n_in,
                              void* d_out, int out_size) {
    const float* x    = (const float*)d_in[0];
    const float* W_ih = (const float*)d_in[1];
    const float* W_hh = (const float*)d_in[2];
    const float* b_ih = (const float*)d_in[3];
    const float* b_hh = (const float*)d_in[4];
    const float* W_fc = (const float*)d_in[5];
    const float* b_fc = (const float*)d_in[6];
    float* out = (float*)d_out;

    const int smem_b = (16 * HH * 4 + HH + 32) * (int)sizeof(float);  // ~66.6 KB
    cudaFuncSetAttribute(rnn_scan, cudaFuncAttributeMaxDynamicSharedMemorySize, smem_b);

    rnn_xproj<<<512, 256>>>(x, W_ih, b_ih, b_hh);
    rnn_scan<<<BB, 256, smem_b>>>(W_hh, W_fc, b_fc, out);
}

// round 3
// speedup vs baseline: 1.0989x; 1.0989x over previous
#include <cuda_runtime.h>
#include <cstring>

#define BB 128
#define TT 512
#define II 128
#define HH 256

__device__ float g_xp[(size_t)BB * TT * HH];   // [B][T][H] fp32, 64 MB scratch

// Packed fp32x2 FMA (sm_103a): two FMA lanes per issue, rt_SMSP=2 like FFMA.
__device__ __forceinline__ float2 ffma2(float2 a, float2 b, float2 c) {
    unsigned long long ua, ub, uc, ud;
    memcpy(&ua, &a, 8); memcpy(&ub, &b, 8); memcpy(&uc, &c, 8);
    asm("fma.rn.f32x2 %0, %1, %2, %3;" : "=l"(ud) : "l"(ua), "l"(ub), "l"(uc));
    float2 d; memcpy(&d, &ud, 8); return d;
}

// ---------------------------------------------------------------------------
// Phase 1: xp[r,h] = x[r,:] . W_ih[h,:] + (b_ih[h] + b_hh[h]),  r in [0, B*T)
// 128 CTAs (one wave) x 256 threads; each CTA does 512 rows (64 tiles of 8).
// Thread h keeps W_ih row h in regs. x tiles double-buffered in SMEM so the
// next tile's GMEM load overlaps the current tile's FMA work (1 bar/tile).
// ---------------------------------------------------------------------------
__global__ void __launch_bounds__(256, 1)
rnn_xproj(const float* __restrict__ x,
          const float* __restrict__ W_ih,
          const float* __restrict__ b_ih,
          const float* __restrict__ b_hh) {
    __shared__ float xs[2][8 * II];          // 2 x 4 KB

    const int h = threadIdx.x;

    const float4* Wi4 = (const float4*)W_ih;
    float4 wreg[32];
#pragma unroll
    for (int q = 0; q < 32; q++) wreg[q] = Wi4[h * 32 + q];

    const float bias = b_ih[h] + b_hh[h];
    const size_t base_row = (size_t)blockIdx.x * 512;

    // preload tile 0
    ((float4*)xs[0])[h] = ((const float4*)(x + base_row * II))[h];
    __syncthreads();

    for (int tile = 0; tile < 64; tile++) {
        const int cur = tile & 1;
        if (tile < 63) {   // prefetch next tile into the other buffer
            ((float4*)xs[cur ^ 1])[h] =
                ((const float4*)(x + (base_row + (size_t)(tile + 1) * 8) * II))[h];
        }

        const size_t r0 = base_row + (size_t)tile * 8;
#pragma unroll
        for (int r = 0; r < 8; r += 2) {
            const float4* x0 = (const float4*)(xs[cur] + r * II);
            const float4* x1 = (const float4*)(xs[cur] + (r + 1) * II);
            float2 a0 = make_float2(bias, 0.0f), a1 = make_float2(0.0f, 0.0f);
            float2 c0 = make_float2(bias, 0.0f), c1 = make_float2(0.0f, 0.0f);
#pragma unroll
            for (int q = 0; q < 32; q++) {
                float4 xv = x0[q], yv = x1[q];
                float2 wlo = make_float2(wreg[q].x, wreg[q].y);
                float2 whi = make_float2(wreg[q].z, wreg[q].w);
                a0 = ffma2(make_float2(xv.x, xv.y), wlo, a0);
                a1 = ffma2(make_float2(xv.z, xv.w), whi, a1);
                c0 = ffma2(make_float2(yv.x, yv.y), wlo, c0);
                c1 = ffma2(make_float2(yv.z, yv.w), whi, c1);
            }
            g_xp[(r0 + r) * HH + h]     = (a0.x + a0.y) + (a1.x + a1.y);
            g_xp[(r0 + r + 1) * HH + h] = (c0.x + c0.y) + (c1.x + c1.y);
        }
        __syncthreads();   // tile done; prefetched buffer now safe to read
    }
}

// ---------------------------------------------------------------------------
// Phase 2 + 3: recurrent scan, 128 CTAs (one per batch row) x 256 threads.
//   W_hh[j][0:192] in regs (48 float4/thread), [192:256] in SMEM [q][j] f4.
//   h double-buffered in SMEM -> ONE __syncthreads per step.
//   4 accumulator chains; SMEM W-tail partial first (latency overlap).
// ---------------------------------------------------------------------------
__global__ void __launch_bounds__(256, 1)
rnn_scan(const float* __restrict__ W_hh,
         const float* __restrict__ W_fc,
         const float* __restrict__ b_fc,
         float* __restrict__ out) {
    extern __shared__ float sm[];
    float4* wt4 = (float4*)sm;               // [16][256] float4 = 64 KB
    float*  hA  = sm + 16 * HH * 4;          // 256 floats
    float*  hB  = hA + HH;                   // 256 floats
    float*  red = hB + HH;                   // 8 floats

    const int j = threadIdx.x;
    const int b = blockIdx.x;

    const float4* W4 = (const float4*)W_hh;  // row j = W4[j*64 .. j*64+63]

    float4 wreg[48];
#pragma unroll
    for (int q = 0; q < 48; q++) wreg[q] = W4[j * 64 + q];

    for (int idx = j; idx < 16 * 256; idx += 256) {
        const int q16 = idx >> 8;
        const int j2  = idx & 255;
        wt4[q16 * 256 + j2] = W4[j2 * 64 + 48 + q16];
    }

    hA[j] = 0.0f;
    __syncthreads();

    const float* xp = g_xp + (size_t)b * TT * HH + j;
    float* hcur = hA;
    float* hnxt = hB;
    float hn = 0.0f;

    for (int t = 0; t < TT; t++) {
        const float xpv = xp[(size_t)t * HH];   // issued early, used after dot

        const float4* h4p = (const float4*)hcur;
        float2 a0 = make_float2(0.0f, 0.0f), a1 = a0, a2 = a0, a3 = a0;

        // SMEM W-tail partial first: its LDS latency hides under the reg-W FMAs
#pragma unroll
        for (int q = 0; q < 16; q++) {
            float4 h4 = h4p[48 + q];
            float4 w4 = wt4[q * 256 + j];
            if (q & 1) {
                a2 = ffma2(make_float2(h4.x, h4.y), make_float2(w4.x, w4.y), a2);
                a3 = ffma2(make_float2(h4.z, h4.w), make_float2(w4.z, w4.w), a3);
            } else {
                a0 = ffma2(make_float2(h4.x, h4.y), make_float2(w4.x, w4.y), a0);
                a1 = ffma2(make_float2(h4.z, h4.w), make_float2(w4.z, w4.w), a1);
            }
        }
#pragma unroll
        for (int q = 0; q < 48; q++) {
            float4 h4 = h4p[q];
            if (q & 1) {
                a2 = ffma2(make_float2(h4.x, h4.y), make_float2(wreg[q].x, wreg[q].y), a2);
                a3 = ffma2(make_float2(h4.z, h4.w), make_float2(wreg[q].z, wreg[q].w), a3);
            } else {
                a0 = ffma2(make_float2(h4.x, h4.y), make_float2(wreg[q].x, wreg[q].y), a0);
                a1 = ffma2(make_float2(h4.z, h4.w), make_float2(wreg[q].z, wreg[q].w), a1);
            }
        }

        const float s = ((a0.x + a0.y) + (a1.x + a1.y)) +
                        ((a2.x + a2.y) + (a3.x + a3.y));
        hn = tanhf(xpv + s);

        hnxt[j] = hn;          // other buffer: safe while peers still read hcur
        __syncthreads();       // publishes hnxt; all hcur reads are done above

        float* tmp = hcur; hcur = hnxt; hnxt = tmp;
    }

    // Phase 3: out[b] = sigmoid(h . W_fc + b_fc)
    float v = hn * W_fc[j];
#pragma unroll
    for (int o = 16; o > 0; o >>= 1) v += __shfl_down_sync(0xffffffffu, v, o);
    if ((j & 31) == 0) red[j >> 5] = v;
    __syncthreads();
    if (j == 0) {
        float s = b_fc[0];
#pragma unroll
        for (int w = 0; w < 8; w++) s += red[w];
        out[b] = 1.0f / (1.0f + expf(-s));
    }
}

// ---------------------------------------------------------------------------

extern "C" void kernel_launch(void* const* d_in, const int* in_sizes, int n_in,
                              void* d_out, int out_size) {
    const float* x    = (const float*)d_in[0];
    const float* W_ih = (const float*)d_in[1];
    const float* W_hh = (const float*)d_in[2];
    const float* b_ih = (const float*)d_in[3];
    const float* b_hh = (const float*)d_in[4];
    const float* W_fc = (const float*)d_in[5];
    const float* b_fc = (const float*)d_in[6];
    float* out = (float*)d_out;

    const int smem_b = (16 * HH * 4 + 2 * HH + 32) * (int)sizeof(float);  // ~67 KB
    cudaFuncSetAttribute(rnn_scan, cudaFuncAttributeMaxDynamicSharedMemorySize, smem_b);

    rnn_xproj<<<128, 256>>>(x, W_ih, b_ih, b_hh);
    rnn_scan<<<BB, 256, smem_b>>>(W_hh, W_fc, b_fc, out);
}